// round 6
// baseline (speedup 1.0000x reference)
#include <cuda_runtime.h>
#include <cuda_bf16.h>

// Factorization machine forward:
//   Xw[b]   = sum_k b_vals[b,k] * w[idx[b,k]]
//   XV[b,f] = sum_k x[b,k] * V[idx[b,k], f]
//   X2V2    = sum_k x^2 * V^2
//   p[b]    = 0.5 / sum_k x[b,k] * sum_f (XV^2 - X2V2)
//   out[b]  = sigmoid(bias + Xw + p)
//
// One warp per row. Lane l owns factors [4l, 4l+4) -> one float4 per V row,
// warp reads a contiguous 512B V row per k (coalesced). idx/x staged in smem.

#define FM_B 8192
#define FM_K 200
#define FM_WARPS 8

__global__ __launch_bounds__(FM_WARPS * 32)
void fm_kernel(const int* __restrict__ idx,
               const float* __restrict__ xv,
               const float* __restrict__ bv,
               const float* __restrict__ w,
               const float4* __restrict__ V4,   // V viewed as [1e6][32] float4
               const float* __restrict__ bias,
               float* __restrict__ out)
{
    __shared__ int   sidx[FM_WARPS][FM_K];
    __shared__ float sx  [FM_WARPS][FM_K];

    const int warp = threadIdx.x >> 5;
    const int lane = threadIdx.x & 31;
    const int row  = blockIdx.x * FM_WARPS + warp;
    if (row >= FM_B) return;

    const int*   irow = idx + (long long)row * FM_K;
    const float* xrow = xv  + (long long)row * FM_K;
    const float* brow = bv  + (long long)row * FM_K;

    // Preload idx/x to shared; fold in Xw and Xnorm partials (lane-strided).
    float xw = 0.0f, xs = 0.0f;
    for (int k = lane; k < FM_K; k += 32) {
        int   id = irow[k];
        float x  = xrow[k];
        sidx[warp][k] = id;
        sx  [warp][k] = x;
        xs += x;
        xw += brow[k] * __ldg(&w[id]);   // 4MB table -> L2 resident
    }
    __syncwarp();

    float4 a1 = make_float4(0.f, 0.f, 0.f, 0.f);
    float4 a2 = make_float4(0.f, 0.f, 0.f, 0.f);

#pragma unroll 8
    for (int k = 0; k < FM_K; k++) {
        const int   id = sidx[warp][k];
        const float x  = sx[warp][k];
        const float4 v = __ldg(&V4[(long long)id * 32 + lane]); // 512B/warp, coalesced
        const float x2 = x * x;
        a1.x = fmaf(x, v.x, a1.x);
        a1.y = fmaf(x, v.y, a1.y);
        a1.z = fmaf(x, v.z, a1.z);
        a1.w = fmaf(x, v.w, a1.w);
        a2.x = fmaf(x2, v.x * v.x, a2.x);
        a2.y = fmaf(x2, v.y * v.y, a2.y);
        a2.z = fmaf(x2, v.z * v.z, a2.z);
        a2.w = fmaf(x2, v.w * v.w, a2.w);
    }

    // per-lane contribution to sum_f (XV^2 - X2V2)
    float p = (a1.x * a1.x - a2.x) + (a1.y * a1.y - a2.y)
            + (a1.z * a1.z - a2.z) + (a1.w * a1.w - a2.w);

    // warp tree-reductions
#pragma unroll
    for (int off = 16; off > 0; off >>= 1) {
        p  += __shfl_xor_sync(0xffffffffu, p,  off);
        xw += __shfl_xor_sync(0xffffffffu, xw, off);
        xs += __shfl_xor_sync(0xffffffffu, xs, off);
    }

    if (lane == 0) {
        float logit = bias[0] + xw + 0.5f / xs * p;
        out[row] = 1.0f / (1.0f + __expf(-logit));
    }
}

extern "C" void kernel_launch(void* const* d_in, const int* in_sizes, int n_in,
                              void* d_out, int out_size)
{
    const int*    idx  = (const int*)   d_in[0];   // [B,K] int32
    const float*  xval = (const float*) d_in[1];   // [B,K]
    const float*  bval = (const float*) d_in[2];   // [B,K]
    const float*  w    = (const float*) d_in[3];   // [1e6,1]
    const float4* V4   = (const float4*)d_in[4];   // [1e6,128] -> float4[1e6][32]
    const float*  bias = (const float*) d_in[5];   // [1]
    float* out = (float*)d_out;                    // [B]

    dim3 block(FM_WARPS * 32);
    dim3 grid(FM_B / FM_WARPS);
    fm_kernel<<<grid, block>>>(idx, xval, bval, w, V4, bias, out);
}